// round 2
// baseline (speedup 1.0000x reference)
#include <cuda_runtime.h>
#include <cstdint>

typedef unsigned long long ull;

#define NTOK   16384
#define NMAIN  (NTOK * 2048)

// ---------------- device scratch (static, allocation-free) ----------------
__device__ float g_Wpart[16][32 * 2048];  // 4 MB k-split partials of W
__device__ float g_W[32 * 2048];          // W = pin_w @ down_w   [32][2048]
__device__ float g_b2[32];                // pin_w @ down_b + pin_b
__device__ float g_U[2048 * 32];          // U[o][c] = sum_h up_w[o][h]*pout_w[h][c]
__device__ float g_ub2[2048];             // up_b + up_w @ pout_b
__device__ float g_Table[256 * 2048];     // clip(codebook @ U^T + ub2)

// ---------------- packed fp32x2 helpers ----------------
__device__ __forceinline__ ull pack2(float a, float b) {
    ull r; asm("mov.b64 %0, {%1, %2};" : "=l"(r) : "f"(a), "f"(b)); return r;
}
__device__ __forceinline__ void unpack2(ull v, float &a, float &b) {
    asm("mov.b64 {%0, %1}, %2;" : "=f"(a), "=f"(b) : "l"(v));
}
__device__ __forceinline__ void fma2(ull &d, ull a, ull b) {
    asm("fma.rn.f32x2 %0, %1, %2, %0;" : "+l"(d) : "l"(a), "l"(b));
}

// ================= kernel 1: W partials = pin_w[32,1024] @ down_w[1024,2048]
// grid (8 i-tiles, 16 k-splits) x 256 threads
__global__ void __launch_bounds__(256) kWpart(const float* __restrict__ down_w,
                                              const float* __restrict__ pin_w) {
    __shared__ float sp[64 * 36];   // [hh][c], padded
    int tid = threadIdx.x;
    int i   = blockIdx.x * 256 + tid;
    int h0  = blockIdx.y * 64;
#pragma unroll
    for (int j = 0; j < 8; j++) {
        int e = tid + 256 * j; int c = e >> 6; int hh = e & 63;
        sp[hh * 36 + c] = pin_w[c * 1024 + h0 + hh];
    }
    __syncthreads();
    float acc[32];
#pragma unroll
    for (int c = 0; c < 32; c++) acc[c] = 0.f;
    for (int hh = 0; hh < 64; hh++) {
        float xv = down_w[(size_t)(h0 + hh) * 2048 + i];
        const float4* sp4 = (const float4*)&sp[hh * 36];
#pragma unroll
        for (int j = 0; j < 8; j++) {
            float4 p = sp4[j];
            acc[4*j+0] += xv * p.x; acc[4*j+1] += xv * p.y;
            acc[4*j+2] += xv * p.z; acc[4*j+3] += xv * p.w;
        }
    }
#pragma unroll
    for (int c = 0; c < 32; c++) g_Wpart[blockIdx.y][c * 2048 + i] = acc[c];
}

// ================= kernel 2: reduce W partials (grid 256 x 256)
__global__ void __launch_bounds__(256) kWred() {
    int j = blockIdx.x * 256 + threadIdx.x;
    float s = 0.f;
#pragma unroll
    for (int p = 0; p < 16; p++) s += g_Wpart[p][j];
    g_W[j] = s;
}

// ================= kernel 3: fused bias b2 = pin_w @ down_b + pin_b (1 block)
__global__ void __launch_bounds__(256) kB2(const float* __restrict__ pin_w,
                                           const float* __restrict__ down_b,
                                           const float* __restrict__ pin_b) {
    __shared__ float red[256];
    int tid = threadIdx.x; int c = tid >> 3; int p = tid & 7;
    float s = 0.f;
    for (int h = p; h < 1024; h += 8) s += pin_w[c * 1024 + h] * down_b[h];
    red[tid] = s;
    __syncthreads();
    if (p == 0) {
        float t = 0.f;
#pragma unroll
        for (int q = 0; q < 8; q++) t += red[c * 8 + q];
        g_b2[c] = t + pin_b[c];
    }
}

// ================= kernel 4: U[o][c] = sum_h up_w[o][h]*pout_w[h][c];
//                   ub2[o] = up_b[o] + sum_h up_w[o][h]*pout_b[h]
// grid 256 x 256 (one warp per o)
__global__ void __launch_bounds__(256) kU(const float* __restrict__ up_w,
                                          const float* __restrict__ pout_w,
                                          const float* __restrict__ pout_b,
                                          const float* __restrict__ up_b) {
    int lane = threadIdx.x & 31;
    int o    = blockIdx.x * 8 + (threadIdx.x >> 5);
    float acc[32];
#pragma unroll
    for (int c = 0; c < 32; c++) acc[c] = 0.f;
    float accb = 0.f;
    for (int h = lane; h < 1024; h += 32) {
        float uv = up_w[(size_t)o * 1024 + h];
        const float4* pw4 = (const float4*)(pout_w + h * 32);
#pragma unroll
        for (int j = 0; j < 8; j++) {
            float4 p = pw4[j];
            acc[4*j+0] += uv * p.x; acc[4*j+1] += uv * p.y;
            acc[4*j+2] += uv * p.z; acc[4*j+3] += uv * p.w;
        }
        accb += uv * pout_b[h];
    }
#pragma unroll
    for (int c = 0; c < 32; c++) {
#pragma unroll
        for (int off = 16; off; off >>= 1)
            acc[c] += __shfl_xor_sync(0xffffffffu, acc[c], off);
    }
#pragma unroll
    for (int off = 16; off; off >>= 1)
        accb += __shfl_xor_sync(0xffffffffu, accb, off);
    if (lane == 0) {
#pragma unroll
        for (int c = 0; c < 32; c++) g_U[o * 32 + c] = acc[c];
        g_ub2[o] = up_b[o] + accb;
    }
}

// ================= kernel 5: Table[n][o] = clip(codebook[n]·U[o] + ub2[o])
// grid 2048 x 256
__global__ void __launch_bounds__(256) kTable(const float* __restrict__ codebook) {
    int e = blockIdx.x * 256 + threadIdx.x;
    int n = e >> 11; int o = e & 2047;
    const float4* cb4 = (const float4*)(codebook + n * 32);
    const float4* u4  = (const float4*)(g_U + o * 32);
    float acc = g_ub2[o];
#pragma unroll
    for (int j = 0; j < 8; j++) {
        float4 a = cb4[j], b = u4[j];
        acc += a.x * b.x + a.y * b.y + a.z * b.z + a.w * b.w;
    }
    acc = fminf(fmaxf(acc, -1.f), 1.f);
    g_Table[e] = acc;
}

// ================= kernel 6 (main): z = x@W^T + b2; argmin dist; gather Table
// grid 128 blocks x 256 threads, 128 tokens per block.
// micro-tile: 4 tokens (2 f32x2 pairs) x 4 c per thread.
#define KT  64
#define SXS 132
// smem layout (bytes):
//   sX     float[64*132]   [0, 33792)
//   sWd    ull  [64*34]    [33792, 51200)
//   scb    float[8192]     [51200, 83968)
//   scnorm float[256]      [83968, 84992)
//   sZ     float[128*36]   [84992, 103424)
//   sIdx   int[128]        [103424, 103936)
#define SMEM_Z 103936

__global__ void __launch_bounds__(256, 1) kZ(const float* __restrict__ x,
                                             const float* __restrict__ codebook,
                                             float* __restrict__ out,
                                             long long out_elems) {
    extern __shared__ char smem[];
    float* sX     = (float*)smem;
    ull*   sWd    = (ull*)(smem + 33792);
    float* scb    = (float*)(smem + 51200);
    float* scnorm = (float*)(smem + 83968);
    float* sZ     = (float*)(smem + 84992);
    int*   sIdx   = (int*)(smem + 103424);

    int tid  = threadIdx.x;
    int tok0 = blockIdx.x * 128;

    // load codebook into smem
    {
        const float4* cbg = (const float4*)codebook;
        float4* scb4 = (float4*)scb;
        for (int j = tid; j < 2048; j += 256) scb4[j] = cbg[j];
    }
    __syncthreads();
    // per-code norms
    {
        const float4* r = (const float4*)(scb + tid * 32);
        float s = 0.f;
#pragma unroll
        for (int j = 0; j < 8; j++) {
            float4 v = r[j];
            s += v.x * v.x + v.y * v.y + v.z * v.z + v.w * v.w;
        }
        scnorm[tid] = s;
    }

    int tg = tid & 31, cg = tid >> 5;
    int t0 = tg * 4, c0 = cg * 4;
    ull acc[8];
#pragma unroll
    for (int i = 0; i < 8; i++) acc[i] = 0ull;

    int trow = tid >> 1, thalf = tid & 1;

    for (int kt = 0; kt < 32; kt++) {
        __syncthreads();
        // load x tile transposed: sX[k][tok]
        {
            const float4* xr = (const float4*)(x + (size_t)(tok0 + trow) * 2048 + kt * 64);
#pragma unroll
            for (int i = 0; i < 8; i++) {
                int kq = thalf * 8 + i;
                float4 v = xr[kq];
                int kb = kq * 4;
                sX[(kb + 0) * SXS + trow] = v.x;
                sX[(kb + 1) * SXS + trow] = v.y;
                sX[(kb + 2) * SXS + trow] = v.z;
                sX[(kb + 3) * SXS + trow] = v.w;
            }
        }
        // load duplicated W tile: sWd[kk][c] = {W[c][k], W[c][k]}
        {
#pragma unroll
            for (int i = 0; i < 8; i++) {
                int e = tid + 256 * i; int c = e >> 6; int kk = e & 63;
                float wv = g_W[c * 2048 + kt * 64 + kk];
                sWd[kk * 34 + c] = pack2(wv, wv);
            }
        }
        __syncthreads();
#pragma unroll 8
        for (int kk = 0; kk < KT; kk++) {
            ulonglong2 xv  = *(const ulonglong2*)&sX[kk * SXS + t0];
            ulonglong2 w01 = *(const ulonglong2*)&sWd[kk * 34 + c0];
            ulonglong2 w23 = *(const ulonglong2*)&sWd[kk * 34 + c0 + 2];
            fma2(acc[0], xv.x, w01.x); fma2(acc[1], xv.x, w01.y);
            fma2(acc[2], xv.x, w23.x); fma2(acc[3], xv.x, w23.y);
            fma2(acc[4], xv.y, w01.x); fma2(acc[5], xv.y, w01.y);
            fma2(acc[6], xv.y, w23.x); fma2(acc[7], xv.y, w23.y);
        }
    }

    // write z (+bias) to smem
    {
        float b2v[4];
#pragma unroll
        for (int j = 0; j < 4; j++) b2v[j] = g_b2[c0 + j];
#pragma unroll
        for (int j = 0; j < 4; j++) {
            float ze, zo;
            unpack2(acc[j], ze, zo);
            sZ[(t0 + 0) * 36 + c0 + j] = ze + b2v[j];
            sZ[(t0 + 1) * 36 + c0 + j] = zo + b2v[j];
            unpack2(acc[4 + j], ze, zo);
            sZ[(t0 + 2) * 36 + c0 + j] = ze + b2v[j];
            sZ[(t0 + 3) * 36 + c0 + j] = zo + b2v[j];
        }
    }
    __syncthreads();

    // argmin: 2 threads per token, 128 codes each
    {
        int tok = tid >> 1, half = tid & 1;
        ull z2[16];
        {
            const float* zr = sZ + tok * 36;
#pragma unroll
            for (int j = 0; j < 16; j++)
                z2[j] = pack2(-2.f * zr[2 * j], -2.f * zr[2 * j + 1]);
        }
        float best = 3.4e38f; int bestn = 0;
        int nbase = half * 128;
        for (int nn = 0; nn < 128; nn++) {
            int n = nbase + nn;
            const ulonglong2* cb2 = (const ulonglong2*)(scb + n * 32);
            ull a0 = 0ull, a1 = 0ull;
#pragma unroll
            for (int j = 0; j < 8; j++) {
                ulonglong2 c2 = cb2[j];
                fma2(a0, z2[2 * j], c2.x);
                fma2(a1, z2[2 * j + 1], c2.y);
            }
            float l0, h0, l1, h1;
            unpack2(a0, l0, h0); unpack2(a1, l1, h1);
            float d = scnorm[n] + ((l0 + h0) + (l1 + h1));
            if (d < best) { best = d; bestn = n; }
        }
        float obest = __shfl_down_sync(0xffffffffu, best, 1);
        int   obn   = __shfl_down_sync(0xffffffffu, bestn, 1);
        if (half == 0) {
            if (obest < best) bestn = obn;   // upper half has larger n -> strict <
            sIdx[tok] = bestn;
        }
    }
    __syncthreads();

    // gather output rows from Table
    {
        const float4* T4 = (const float4*)g_Table;
        float4* out4 = (float4*)out;
        for (int e = tid; e < 128 * 512; e += 256) {
            int tok = e >> 9; int o4 = e & 511;
            out4[(size_t)(tok0 + tok) * 512 + o4] = T4[(size_t)sIdx[tok] * 512 + o4];
        }
        // optional tail: indices (as float) and commit_loss, if the output
        // buffer carries them
        if (tid < 128) {
            long long pos = (long long)NMAIN + tok0 + tid;
            if (pos < out_elems) out[pos] = (float)sIdx[tid];
        }
        if (blockIdx.x == 0 && tid == 0) {
            long long pos = (long long)NMAIN + NTOK;
            if (pos < out_elems) out[pos] = 0.f;
        }
    }
}

// ================= launch =================
extern "C" void kernel_launch(void* const* d_in, const int* in_sizes, int n_in,
                              void* d_out, int out_size) {
    const float* x        = (const float*)d_in[0];
    const float* down_w   = (const float*)d_in[1];
    const float* down_b   = (const float*)d_in[2];
    const float* pin_w    = (const float*)d_in[3];
    const float* pin_b    = (const float*)d_in[4];
    const float* codebook = (const float*)d_in[5];
    const float* pout_w   = (const float*)d_in[6];
    const float* pout_b   = (const float*)d_in[7];
    const float* up_w     = (const float*)d_in[8];
    const float* up_b     = (const float*)d_in[9];
    float* out = (float*)d_out;

    cudaFuncSetAttribute(kZ, cudaFuncAttributeMaxDynamicSharedMemorySize, SMEM_Z);

    dim3 gW(8, 16);
    kWpart<<<gW, 256>>>(down_w, pin_w);
    kWred<<<256, 256>>>();
    kB2<<<1, 256>>>(pin_w, down_b, pin_b);
    kU<<<256, 256>>>(up_w, pout_w, pout_b, up_b);
    kTable<<<2048, 256>>>(codebook);
    kZ<<<128, 256, SMEM_Z>>>(x, codebook, out, (long long)out_size);
}

// round 3
// speedup vs baseline: 1.6559x; 1.6559x over previous
#include <cuda_runtime.h>
#include <cstdint>

typedef unsigned long long ull;

#define NTOK   16384
#define NMAIN  (NTOK * 2048)

// ---------------- device scratch (static, allocation-free) ----------------
__device__ float g_Wpart[16][32 * 2048];   // 4 MB k-split partials of W
__device__ float g_W[32 * 2048];           // W = pin_w @ down_w   [32][2048]
__device__ float g_b2[32];                 // pin_w @ down_b + pin_b
__device__ float g_PoutT[32 * 1024];       // pout_w transposed [c][h]
__device__ float g_Upart[16][2048 * 32];   // 4 MB k-split partials of U
__device__ float g_U[2048 * 32];           // U[o][c] = sum_h up_w[o][h]*pout_w[h][c]
__device__ float g_ub2[2048];              // up_b + up_w @ pout_b
__device__ float g_Table[256 * 2048];      // clip(codebook @ U^T + ub2)

// ---------------- helpers ----------------
__device__ __forceinline__ ull pack2(float a, float b) {
    ull r; asm("mov.b64 %0, {%1, %2};" : "=l"(r) : "f"(a), "f"(b)); return r;
}
__device__ __forceinline__ void unpack2(ull v, float &a, float &b) {
    asm("mov.b64 {%0, %1}, %2;" : "=f"(a), "=f"(b) : "l"(v));
}
__device__ __forceinline__ void fma2(ull &d, ull a, ull b) {
    asm("fma.rn.f32x2 %0, %1, %2, %0;" : "+l"(d) : "l"(a), "l"(b));
}
__device__ __forceinline__ uint32_t smem_u32(const void* p) {
    uint32_t a;
    asm("{ .reg .u64 t; cvta.to.shared.u64 t, %1; cvt.u32.u64 %0, t; }" : "=r"(a) : "l"(p));
    return a;
}
__device__ __forceinline__ void cpa16(uint32_t s, const void* g) {
    asm volatile("cp.async.cg.shared.global [%0], [%1], 16;" :: "r"(s), "l"(g));
}

// ================= kernel 1: W partials = pin_w[32,1024] @ down_w[1024,2048]
// fma2 paired over c. grid (8 i-tiles, 16 k-splits) x 256 threads
__global__ void __launch_bounds__(256) kWpart(const float* __restrict__ down_w,
                                              const float* __restrict__ pin_w) {
    __shared__ ull spd[64 * 18];   // [hh][cpair], stride 18 (16B-aligned rows)
    int tid = threadIdx.x;
    int i   = blockIdx.x * 256 + tid;
    int h0  = blockIdx.y * 64;
#pragma unroll
    for (int j = 0; j < 4; j++) {
        int e = tid + 256 * j;                 // 0..1023
        int hh = e >> 4, cp = e & 15;
        spd[hh * 18 + cp] = pack2(pin_w[(2 * cp) * 1024 + h0 + hh],
                                  pin_w[(2 * cp + 1) * 1024 + h0 + hh]);
    }
    __syncthreads();
    ull acc2[16];
#pragma unroll
    for (int c = 0; c < 16; c++) acc2[c] = 0ull;
    for (int hh = 0; hh < 64; hh++) {
        float xv = down_w[(size_t)(h0 + hh) * 2048 + i];
        ull x2 = pack2(xv, xv);
        const ulonglong2* w2 = (const ulonglong2*)&spd[hh * 18];
#pragma unroll
        for (int jj = 0; jj < 8; jj++) {
            ulonglong2 w = w2[jj];
            fma2(acc2[2 * jj], x2, w.x);
            fma2(acc2[2 * jj + 1], x2, w.y);
        }
    }
#pragma unroll
    for (int cp = 0; cp < 16; cp++) {
        float a, b; unpack2(acc2[cp], a, b);
        g_Wpart[blockIdx.y][(2 * cp) * 2048 + i]     = a;
        g_Wpart[blockIdx.y][(2 * cp + 1) * 2048 + i] = b;
    }
}

// ================= kernel 2: reduce W partials (grid 256 x 256)
__global__ void __launch_bounds__(256) kWred() {
    int j = blockIdx.x * 256 + threadIdx.x;
    float s = 0.f;
#pragma unroll
    for (int p = 0; p < 16; p++) s += g_Wpart[p][j];
    g_W[j] = s;
}

// ================= kernel 3: b2 = pin_w @ down_b + pin_b (1 block)
__global__ void __launch_bounds__(256) kB2(const float* __restrict__ pin_w,
                                           const float* __restrict__ down_b,
                                           const float* __restrict__ pin_b) {
    __shared__ float red[256];
    int tid = threadIdx.x; int c = tid >> 3; int p = tid & 7;
    float s = 0.f;
    for (int h = p; h < 1024; h += 8) s += pin_w[c * 1024 + h] * down_b[h];
    red[tid] = s;
    __syncthreads();
    if (p == 0) {
        float t = 0.f;
#pragma unroll
        for (int q = 0; q < 8; q++) t += red[c * 8 + q];
        g_b2[c] = t + pin_b[c];
    }
}

// ================= kernel 4: transpose pout_w[h][c] -> g_PoutT[c][h] (grid 128)
__global__ void __launch_bounds__(256) kPT(const float* __restrict__ pout_w) {
    int e = blockIdx.x * 256 + threadIdx.x;    // < 32768
    int h = e >> 5, c = e & 31;
    g_PoutT[c * 1024 + h] = pout_w[e];
}

// ================= kernel 5: U partials = up_w[2048,1024] @ PoutT^T
// grid (16 o-tiles, 16 k-splits) x 256.  Same fma2-k-paired core as kZ.
__global__ void __launch_bounds__(256) kU2(const float* __restrict__ up_w) {
    __shared__ float sA[2 * 4096];   // [o 128][k 32] swizzled, 2 tiles
    __shared__ float sB[2 * 1024];   // [c 32][k 32]
    int tid = threadIdx.x;
    int o0 = blockIdx.x * 128;
    int k0base = blockIdx.y * 64;
#pragma unroll
    for (int tile = 0; tile < 2; tile++) {
        int k0 = k0base + tile * 32;
#pragma unroll
        for (int j = 0; j < 4; j++) {
            int idx = tid + 256 * j;
            int t = idx >> 3, q = idx & 7;
            int col = q ^ ((t ^ (t >> 3)) & 7);
            *(float4*)(sA + tile * 4096 + t * 32 + col * 4) =
                *(const float4*)(up_w + (size_t)(o0 + t) * 1024 + k0 + q * 4);
        }
        {
            int c = tid >> 3, q = tid & 7;
            *(float4*)(sB + tile * 1024 + c * 32 + q * 4) =
                *(const float4*)(g_PoutT + c * 1024 + k0 + q * 4);
        }
    }
    __syncthreads();
    int tg = tid & 31, cg = tid >> 5;
    ull acc[16];
#pragma unroll
    for (int i = 0; i < 16; i++) acc[i] = 0ull;
#pragma unroll
    for (int tile = 0; tile < 2; tile++) {
        const float* bx = sA + tile * 4096;
        const float* bw = sB + tile * 1024;
#pragma unroll
        for (int q = 0; q < 8; q++) {
            ulonglong2 xv[4], wv[4];
#pragma unroll
            for (int i = 0; i < 4; i++) {
                int t = tg * 4 + i;
                int col = q ^ ((t ^ (t >> 3)) & 7);
                xv[i] = *(const ulonglong2*)(bx + t * 32 + col * 4);
            }
#pragma unroll
            for (int j = 0; j < 4; j++)
                wv[j] = *(const ulonglong2*)(bw + (cg * 4 + j) * 32 + q * 4);
#pragma unroll
            for (int i = 0; i < 4; i++)
#pragma unroll
                for (int j = 0; j < 4; j++) fma2(acc[i * 4 + j], xv[i].x, wv[j].x);
#pragma unroll
            for (int i = 0; i < 4; i++)
#pragma unroll
                for (int j = 0; j < 4; j++) fma2(acc[i * 4 + j], xv[i].y, wv[j].y);
        }
    }
    __syncthreads();
    float* sU = sA;   // reuse [128][32]
#pragma unroll
    for (int i = 0; i < 4; i++)
#pragma unroll
        for (int j = 0; j < 4; j++) {
            float lo, hi; unpack2(acc[i * 4 + j], lo, hi);
            sU[(tg * 4 + i) * 32 + cg * 4 + j] = lo + hi;
        }
    __syncthreads();
    float4* dst = (float4*)(g_Upart[blockIdx.y] + (size_t)o0 * 32);
    const float4* src = (const float4*)sU;
#pragma unroll
    for (int j = 0; j < 4; j++) { int e = tid + 256 * j; dst[e] = src[e]; }
}

// ================= kernel 6: reduce U partials (grid 256 x 256)
__global__ void __launch_bounds__(256) kUred() {
    int e = blockIdx.x * 256 + threadIdx.x;
    float s = 0.f;
#pragma unroll
    for (int p = 0; p < 16; p++) s += g_Upart[p][e];
    g_U[e] = s;
}

// ================= kernel 7: ub2[o] = up_b[o] + up_w[o]·pout_b  (grid 256)
__global__ void __launch_bounds__(256) kUb(const float* __restrict__ up_w,
                                           const float* __restrict__ pout_b,
                                           const float* __restrict__ up_b) {
    int lane = threadIdx.x & 31;
    int o = blockIdx.x * 8 + (threadIdx.x >> 5);
    float s = 0.f;
    for (int h = lane; h < 1024; h += 32) s += up_w[(size_t)o * 1024 + h] * pout_b[h];
#pragma unroll
    for (int off = 16; off; off >>= 1) s += __shfl_xor_sync(0xffffffffu, s, off);
    if (lane == 0) g_ub2[o] = up_b[o] + s;
}

// ================= kernel 8: Table[n][o] = clip(codebook[n]·U[o] + ub2[o])
__global__ void __launch_bounds__(256) kTable(const float* __restrict__ codebook) {
    int e = blockIdx.x * 256 + threadIdx.x;
    int n = e >> 11; int o = e & 2047;
    const float4* cb4 = (const float4*)(codebook + n * 32);
    const float4* u4  = (const float4*)(g_U + o * 32);
    float acc = g_ub2[o];
#pragma unroll
    for (int j = 0; j < 8; j++) {
        float4 a = cb4[j], b = u4[j];
        acc += a.x * b.x + a.y * b.y + a.z * b.z + a.w * b.w;
    }
    g_Table[e] = fminf(fmaxf(acc, -1.f), 1.f);
}

// ================= kernel 9 (main): z = x@W^T + b2 ; argmin ; gather
// grid 128 x 256 threads. 128 tokens/block. fma2 paired over K.
// dyn smem layout (bytes):
//   sX  2 x 16384  [0, 32768)       (reused as sZ, stride 34, after GEMM)
//   sW  2 x  4096  [32768, 40960)
//   scb 32768      [40960, 73728)
//   scnorm 1024    [73728, 74752)
//   sIdx 512       [74752, 75264)
#define SMEM_Z 75264

__global__ void __launch_bounds__(256, 1) kZ(const float* __restrict__ x,
                                             const float* __restrict__ codebook,
                                             float* __restrict__ out,
                                             long long out_elems) {
    extern __shared__ char smem[];
    float* sXf    = (float*)smem;
    float* sWf    = (float*)(smem + 32768);
    float* scb    = (float*)(smem + 40960);
    float* scnorm = (float*)(smem + 73728);
    int*   sIdx   = (int*)(smem + 74752);
    float* sZ     = (float*)smem;            // stride 34, reuse after GEMM

    int tid  = threadIdx.x;
    int tok0 = blockIdx.x * 128;

    // codebook -> smem
    {
        const float4* cg4 = (const float4*)codebook;
        float4* s4 = (float4*)scb;
#pragma unroll
        for (int j = 0; j < 8; j++) s4[tid + 256 * j] = cg4[tid + 256 * j];
    }

    uint32_t sxu = smem_u32(sXf);
    uint32_t swu = smem_u32(sWf);

#define FILLZ(KT, B) do {                                                        \
        int _k0 = (KT) * 32;                                                     \
        uint32_t _xb = sxu + (B) * 16384u;                                       \
        _Pragma("unroll")                                                        \
        for (int _j = 0; _j < 4; _j++) {                                         \
            int _idx = tid + 256 * _j;                                           \
            int _t = _idx >> 3, _q = _idx & 7;                                   \
            int _col = _q ^ ((_t ^ (_t >> 3)) & 7);                              \
            cpa16(_xb + (uint32_t)(_t * 128 + _col * 16),                        \
                  x + (size_t)(tok0 + _t) * 2048 + _k0 + _q * 4);                \
        }                                                                        \
        { int _c = tid >> 3, _q = tid & 7;                                       \
          cpa16(swu + (B) * 4096u + (uint32_t)(_c * 128 + _q * 16),              \
                g_W + _c * 2048 + _k0 + _q * 4); }                               \
    } while (0)

    FILLZ(0, 0);
    asm volatile("cp.async.commit_group;");

    int tg = tid & 31, cg = tid >> 5;
    ull acc[16];
#pragma unroll
    for (int i = 0; i < 16; i++) acc[i] = 0ull;

    for (int kt = 0; kt < 64; kt++) {
        int b = kt & 1;
        if (kt + 1 < 64) {
            FILLZ(kt + 1, (kt + 1) & 1);
            asm volatile("cp.async.commit_group;");
            asm volatile("cp.async.wait_group 1;");
        } else {
            asm volatile("cp.async.wait_group 0;");
        }
        __syncthreads();
        const float* bx = sXf + b * 4096;
        const float* bw = sWf + b * 1024;
#pragma unroll
        for (int q = 0; q < 8; q++) {
            ulonglong2 xv[4], wv[4];
#pragma unroll
            for (int i = 0; i < 4; i++) {
                int t = tg * 4 + i;
                int col = q ^ ((t ^ (t >> 3)) & 7);
                xv[i] = *(const ulonglong2*)(bx + t * 32 + col * 4);
            }
#pragma unroll
            for (int j = 0; j < 4; j++)
                wv[j] = *(const ulonglong2*)(bw + (cg * 4 + j) * 32 + q * 4);
#pragma unroll
            for (int i = 0; i < 4; i++)
#pragma unroll
                for (int j = 0; j < 4; j++) fma2(acc[i * 4 + j], xv[i].x, wv[j].x);
#pragma unroll
            for (int i = 0; i < 4; i++)
#pragma unroll
                for (int j = 0; j < 4; j++) fma2(acc[i * 4 + j], xv[i].y, wv[j].y);
        }
        __syncthreads();
    }

    // epilogue: z -> sZ (stride 34) with bias
    {
        float b2v[4];
#pragma unroll
        for (int j = 0; j < 4; j++) b2v[j] = g_b2[cg * 4 + j];
#pragma unroll
        for (int i = 0; i < 4; i++) {
            int t = tg * 4 + i;
#pragma unroll
            for (int j = 0; j < 4; j++) {
                float lo, hi; unpack2(acc[i * 4 + j], lo, hi);
                sZ[t * 34 + cg * 4 + j] = lo + hi + b2v[j];
            }
        }
    }
    // per-code norms
    {
        const float4* r = (const float4*)(scb + tid * 32);
        float s = 0.f;
#pragma unroll
        for (int j = 0; j < 8; j++) {
            float4 v = r[j];
            s += v.x * v.x + v.y * v.y + v.z * v.z + v.w * v.w;
        }
        scnorm[tid] = s;
    }
    __syncthreads();

    // argmin: 2 threads per token, 128 codes each
    {
        int tok = tid >> 1, half = tid & 1;
        ull z2[16];
        const float* zr = sZ + tok * 34;
#pragma unroll
        for (int j = 0; j < 16; j++)
            z2[j] = pack2(-2.f * zr[2 * j], -2.f * zr[2 * j + 1]);
        float best = 3.4e38f; int bestn = 0;
        int nbase = half * 128;
        for (int nn = 0; nn < 128; nn++) {
            int n = nbase + nn;
            const ulonglong2* cb2 = (const ulonglong2*)(scb + n * 32);
            ull a0 = 0ull, a1 = 0ull;
#pragma unroll
            for (int j = 0; j < 8; j++) {
                ulonglong2 c2 = cb2[j];
                fma2(a0, z2[2 * j], c2.x);
                fma2(a1, z2[2 * j + 1], c2.y);
            }
            float l0, h0, l1, h1;
            unpack2(a0, l0, h0); unpack2(a1, l1, h1);
            float d = scnorm[n] + ((l0 + h0) + (l1 + h1));
            if (d < best) { best = d; bestn = n; }
        }
        float obest = __shfl_down_sync(0xffffffffu, best, 1);
        int   obn   = __shfl_down_sync(0xffffffffu, bestn, 1);
        if (half == 0) {
            if (obest < best) bestn = obn;   // lower half wins ties (first index)
            sIdx[tok] = bestn;
        }
    }
    __syncthreads();

    // gather output rows from Table
    {
        const float4* T4 = (const float4*)g_Table;
        float4* out4 = (float4*)out;
        for (int e = tid; e < 128 * 512; e += 256) {
            int tok = e >> 9; int o4 = e & 511;
            out4[(size_t)(tok0 + tok) * 512 + o4] = T4[(size_t)sIdx[tok] * 512 + o4];
        }
        if (tid < 128) {
            long long pos = (long long)NMAIN + tok0 + tid;
            if (pos < out_elems) out[pos] = (float)sIdx[tid];
        }
        if (blockIdx.x == 0 && tid == 0) {
            long long pos = (long long)NMAIN + NTOK;
            if (pos < out_elems) out[pos] = 0.f;
        }
    }
}

// ================= launch =================
extern "C" void kernel_launch(void* const* d_in, const int* in_sizes, int n_in,
                              void* d_out, int out_size) {
    const float* x        = (const float*)d_in[0];
    const float* down_w   = (const float*)d_in[1];
    const float* down_b   = (const float*)d_in[2];
    const float* pin_w    = (const float*)d_in[3];
    const float* pin_b    = (const float*)d_in[4];
    const float* codebook = (const float*)d_in[5];
    const float* pout_w   = (const float*)d_in[6];
    const float* pout_b   = (const float*)d_in[7];
    const float* up_w     = (const float*)d_in[8];
    const float* up_b     = (const float*)d_in[9];
    float* out = (float*)d_out;

    cudaFuncSetAttribute(kZ, cudaFuncAttributeMaxDynamicSharedMemorySize, SMEM_Z);

    kWpart<<<dim3(8, 16), 256>>>(down_w, pin_w);
    kWred<<<256, 256>>>();
    kB2<<<1, 256>>>(pin_w, down_b, pin_b);
    kPT<<<128, 256>>>(pout_w);
    kU2<<<dim3(16, 16), 256>>>(up_w);
    kUred<<<256, 256>>>();
    kUb<<<256, 256>>>(up_w, pout_b, up_b);
    kTable<<<2048, 256>>>(codebook);
    kZ<<<128, 256, SMEM_Z>>>(x, codebook, out, (long long)out_size);
}

// round 4
// speedup vs baseline: 1.9399x; 1.1715x over previous
#include <cuda_runtime.h>
#include <cstdint>

typedef unsigned long long ull;

#define NTOK   16384
#define NMAIN  (NTOK * 2048)

// ---------------- device scratch (static, allocation-free) ----------------
__device__ float g_Wpart[16][32 * 2048];   // 4 MB k-split partials of W
__device__ float g_W[32 * 2048];           // W = pin_w @ down_w   [32][2048]
__device__ float g_b2[32];                 // pin_w @ down_b + pin_b
__device__ float g_Upart[16][2048 * 32];   // 4 MB k-split partials of U
__device__ float g_U[2048 * 32];           // U[o][c] = sum_h up_w[o][h]*pout_w[h][c]
__device__ float g_ub2[2048];              // up_b + up_w @ pout_b
__device__ float g_Table[256 * 2048];      // clip(codebook @ U^T + ub2)

// ---------------- helpers ----------------
__device__ __forceinline__ ull pack2(float a, float b) {
    ull r; asm("mov.b64 %0, {%1, %2};" : "=l"(r) : "f"(a), "f"(b)); return r;
}
__device__ __forceinline__ void unpack2(ull v, float &a, float &b) {
    asm("mov.b64 {%0, %1}, %2;" : "=f"(a), "=f"(b) : "l"(v));
}
__device__ __forceinline__ void fma2(ull &d, ull a, ull b) {
    asm("fma.rn.f32x2 %0, %1, %2, %0;" : "+l"(d) : "l"(a), "l"(b));
}
__device__ __forceinline__ uint32_t smem_u32(const void* p) {
    uint32_t a;
    asm("{ .reg .u64 t; cvta.to.shared.u64 t, %1; cvt.u32.u64 %0, t; }" : "=r"(a) : "l"(p));
    return a;
}
__device__ __forceinline__ void cpa16(uint32_t s, const void* g) {
    asm volatile("cp.async.cg.shared.global [%0], [%1], 16;" :: "r"(s), "l"(g));
}

// ================= kPre1: W partials (blocks 0..127) + U partials (128..383)
__global__ void __launch_bounds__(256) kPre1(const float* __restrict__ down_w,
                                             const float* __restrict__ pin_w,
                                             const float* __restrict__ up_w,
                                             const float* __restrict__ pout_w) {
    __shared__ char sbuf[43008];
    int tid = threadIdx.x;

    if (blockIdx.x < 128) {
        // ---- W partials: pin_w[32,1024] @ down_w[1024,2048]
        ull* spd = (ull*)sbuf;                 // [hh][cpair], stride 18
        int b  = blockIdx.x;
        int i  = (b & 7) * 256 + tid;
        int h0 = (b >> 3) * 64;
#pragma unroll
        for (int j = 0; j < 4; j++) {
            int e = tid + 256 * j;
            int hh = e >> 4, cp = e & 15;
            spd[hh * 18 + cp] = pack2(pin_w[(2 * cp) * 1024 + h0 + hh],
                                      pin_w[(2 * cp + 1) * 1024 + h0 + hh]);
        }
        __syncthreads();
        ull acc2[16];
#pragma unroll
        for (int c = 0; c < 16; c++) acc2[c] = 0ull;
        for (int hh = 0; hh < 64; hh++) {
            float xv = down_w[(size_t)(h0 + hh) * 2048 + i];
            ull x2 = pack2(xv, xv);
            const ulonglong2* w2 = (const ulonglong2*)&spd[hh * 18];
#pragma unroll
            for (int jj = 0; jj < 8; jj++) {
                ulonglong2 w = w2[jj];
                fma2(acc2[2 * jj], x2, w.x);
                fma2(acc2[2 * jj + 1], x2, w.y);
            }
        }
#pragma unroll
        for (int cp = 0; cp < 16; cp++) {
            float a, b2; unpack2(acc2[cp], a, b2);
            g_Wpart[b >> 3][(2 * cp) * 2048 + i]     = a;
            g_Wpart[b >> 3][(2 * cp + 1) * 2048 + i] = b2;
        }
    } else {
        // ---- U partials: up_w[2048,1024] @ pout_w^T  (pout_w is [h][c])
        float* sA = (float*)sbuf;              // [o 128][k 32] swizzled, 2 tiles
        float* sB = (float*)(sbuf + 32768);    // [c 32][k] stride 40, 2 tiles
        int b2i = blockIdx.x - 128;
        int o0 = (b2i & 15) * 128;
        int k0base = (b2i >> 4) * 64;
#pragma unroll
        for (int tile = 0; tile < 2; tile++) {
            int k0 = k0base + tile * 32;
#pragma unroll
            for (int j = 0; j < 4; j++) {
                int idx = tid + 256 * j;
                int t = idx >> 3, q = idx & 7;
                int col = q ^ ((t ^ (t >> 3)) & 7);
                *(float4*)(sA + tile * 4096 + t * 32 + col * 4) =
                    *(const float4*)(up_w + (size_t)(o0 + t) * 1024 + k0 + q * 4);
            }
#pragma unroll
            for (int j = 0; j < 4; j++) {       // transpose-load pout_w
                int idx = tid + 256 * j;
                int kk = idx >> 5, c = idx & 31;
                sB[tile * 1280 + c * 40 + kk] = pout_w[(size_t)(k0 + kk) * 32 + c];
            }
        }
        __syncthreads();
        int tg = tid & 31, cg = tid >> 5;
        ull acc[16];
#pragma unroll
        for (int i = 0; i < 16; i++) acc[i] = 0ull;
#pragma unroll
        for (int tile = 0; tile < 2; tile++) {
            const float* bx = sA + tile * 4096;
            const float* bw = sB + tile * 1280;
#pragma unroll
            for (int q = 0; q < 8; q++) {
                ulonglong2 xv[4], wv[4];
#pragma unroll
                for (int i = 0; i < 4; i++) {
                    int t = tg * 4 + i;
                    int col = q ^ ((t ^ (t >> 3)) & 7);
                    xv[i] = *(const ulonglong2*)(bx + t * 32 + col * 4);
                }
#pragma unroll
                for (int j = 0; j < 4; j++)
                    wv[j] = *(const ulonglong2*)(bw + (cg * 4 + j) * 40 + q * 4);
#pragma unroll
                for (int i = 0; i < 4; i++)
#pragma unroll
                    for (int j = 0; j < 4; j++) {
                        fma2(acc[i * 4 + j], xv[i].x, wv[j].x);
                        fma2(acc[i * 4 + j], xv[i].y, wv[j].y);
                    }
            }
        }
        __syncthreads();
        float* sU = sA;   // reuse [128][32]
#pragma unroll
        for (int i = 0; i < 4; i++)
#pragma unroll
            for (int j = 0; j < 4; j++) {
                float lo, hi; unpack2(acc[i * 4 + j], lo, hi);
                sU[(tg * 4 + i) * 32 + cg * 4 + j] = lo + hi;
            }
        __syncthreads();
        float4* dst = (float4*)(g_Upart[b2i >> 4] + (size_t)o0 * 32);
        const float4* src = (const float4*)sU;
#pragma unroll
        for (int j = 0; j < 4; j++) { int e = tid + 256 * j; dst[e] = src[e]; }
    }
}

// ================= kPre2: Wred(0..255) + b2(256) + Ured(257..512) + ub2(513..768)
__global__ void __launch_bounds__(256) kPre2(const float* __restrict__ pin_w,
                                             const float* __restrict__ down_b,
                                             const float* __restrict__ pin_b,
                                             const float* __restrict__ up_w,
                                             const float* __restrict__ pout_b,
                                             const float* __restrict__ up_b) {
    __shared__ float red[256];
    int tid = threadIdx.x;
    int b = blockIdx.x;
    if (b < 256) {
        int j = b * 256 + tid;
        float s = 0.f;
#pragma unroll
        for (int p = 0; p < 16; p++) s += g_Wpart[p][j];
        g_W[j] = s;
    } else if (b == 256) {
        int c = tid >> 3; int p = tid & 7;
        float s = 0.f;
        for (int h = p; h < 1024; h += 8) s += pin_w[c * 1024 + h] * down_b[h];
        red[tid] = s;
        __syncthreads();
        if (p == 0) {
            float t = 0.f;
#pragma unroll
            for (int q = 0; q < 8; q++) t += red[c * 8 + q];
            g_b2[c] = t + pin_b[c];
        }
    } else if (b < 513) {
        int e = (b - 257) * 256 + tid;
        float s = 0.f;
#pragma unroll
        for (int p = 0; p < 16; p++) s += g_Upart[p][e];
        g_U[e] = s;
    } else {
        int lane = tid & 31;
        int o = (b - 513) * 8 + (tid >> 5);
        float s = 0.f;
        for (int h = lane; h < 1024; h += 32)
            s += up_w[(size_t)o * 1024 + h] * pout_b[h];
#pragma unroll
        for (int off = 16; off; off >>= 1) s += __shfl_xor_sync(0xffffffffu, s, off);
        if (lane == 0) g_ub2[o] = up_b[o] + s;
    }
}

// ================= kTable: Table[n][o] = clip(codebook[n]·U[o] + ub2[o])
__global__ void __launch_bounds__(256) kTable(const float* __restrict__ codebook) {
    int e = blockIdx.x * 256 + threadIdx.x;
    int n = e >> 11; int o = e & 2047;
    const float4* cb4 = (const float4*)(codebook + n * 32);
    const float4* u4  = (const float4*)(g_U + o * 32);
    float acc = g_ub2[o];
#pragma unroll
    for (int j = 0; j < 8; j++) {
        float4 a = cb4[j], b = u4[j];
        acc += a.x * b.x + a.y * b.y + a.z * b.z + a.w * b.w;
    }
    g_Table[e] = fminf(fmaxf(acc, -1.f), 1.f);
}

// ================= kZ (main): z = x@W^T + b2 ; argmin ; gather
// 128 blocks x 256 threads, 128 tokens/block.
// Thread tile: 4 tok x 8 c, split-k across warp halves (warps 0-3: q 0-3,
// warps 4-7: q 4-7). 4-stage cp.async pipeline, 1 barrier per tile.
// dyn smem (bytes):
//   sX  4 x 16384  [0, 65536)    (reused post-loop: sZp@0, sZf@20480, stride 33)
//   sW  4 x  4096  [65536, 81920)
//   scb 32768      [81920, 114688)
//   scnorm 1024    [114688, 115712)
//   sIdx 512       [115712, 116224)
#define SMEM_Z 116224

__global__ void __launch_bounds__(256, 1) kZ(const float* __restrict__ x,
                                             const float* __restrict__ codebook,
                                             float* __restrict__ out,
                                             long long out_elems) {
    extern __shared__ char smem[];
    float* sXf    = (float*)smem;
    float* sWf    = (float*)(smem + 65536);
    float* scb    = (float*)(smem + 81920);
    float* scnorm = (float*)(smem + 114688);
    int*   sIdx   = (int*)(smem + 115712);
    float* sZp    = (float*)smem;             // stride 33
    float* sZf    = (float*)(smem + 20480);   // stride 33

    int tid  = threadIdx.x;
    int tok0 = blockIdx.x * 128;
    uint32_t sxu = smem_u32(sXf);
    uint32_t swu = smem_u32(sWf);

#define FILLZ(KT, B) do {                                                        \
        int _k0 = (KT) * 32;                                                     \
        uint32_t _xb = sxu + (unsigned)(B) * 16384u;                             \
        _Pragma("unroll")                                                        \
        for (int _j = 0; _j < 4; _j++) {                                         \
            int _idx = tid + 256 * _j;                                           \
            int _t = _idx >> 3, _q = _idx & 7;                                   \
            int _col = _q ^ ((_t ^ (_t >> 3)) & 7);                              \
            cpa16(_xb + (uint32_t)(_t * 128 + _col * 16),                        \
                  x + (size_t)(tok0 + _t) * 2048 + _k0 + _q * 4);                \
        }                                                                        \
        { int _c = tid >> 3, _q = tid & 7;                                       \
          cpa16(swu + (unsigned)(B) * 4096u + (uint32_t)(_c * 128 + _q * 16),    \
                g_W + _c * 2048 + _k0 + _q * 4); }                               \
    } while (0)

    FILLZ(0, 0); asm volatile("cp.async.commit_group;");
    FILLZ(1, 1); asm volatile("cp.async.commit_group;");
    FILLZ(2, 2); asm volatile("cp.async.commit_group;");

    // codebook -> smem (overlaps with cp.async)
    {
        const float4* cg4 = (const float4*)codebook;
        float4* s4 = (float4*)scb;
#pragma unroll
        for (int j = 0; j < 8; j++) s4[tid + 256 * j] = cg4[tid + 256 * j];
    }

    int lane = tid & 31, warp = tid >> 5;
    int c0 = (warp & 3) * 8;
    int kbase = (warp >> 2) * 4;     // q range [kbase, kbase+4)
    int t0 = lane * 4;
    int swzv[4];
#pragma unroll
    for (int i = 0; i < 4; i++) {
        int t = t0 + i;
        swzv[i] = (t ^ (t >> 3)) & 7;
    }

    ull acc[32];
#pragma unroll
    for (int i = 0; i < 32; i++) acc[i] = 0ull;

    for (int kt = 0; kt < 64; kt++) {
        if (kt < 62)      asm volatile("cp.async.wait_group 2;");
        else if (kt == 62) asm volatile("cp.async.wait_group 1;");
        else              asm volatile("cp.async.wait_group 0;");
        __syncthreads();
        const float* bx = sXf + (kt & 3) * 4096;
        const float* bw = sWf + (kt & 3) * 1024;
#pragma unroll
        for (int qq = 0; qq < 4; qq++) {
            int q = kbase + qq;
            ulonglong2 xv[4];
#pragma unroll
            for (int i = 0; i < 4; i++)
                xv[i] = *(const ulonglong2*)(bx + (t0 + i) * 32 + (q ^ swzv[i]) * 4);
#pragma unroll
            for (int jh = 0; jh < 2; jh++) {
                ulonglong2 wv[4];
#pragma unroll
                for (int j = 0; j < 4; j++)
                    wv[j] = *(const ulonglong2*)(bw + (c0 + jh * 4 + j) * 32 + q * 4);
#pragma unroll
                for (int i = 0; i < 4; i++)
#pragma unroll
                    for (int j = 0; j < 4; j++) {
                        fma2(acc[i * 8 + jh * 4 + j], xv[i].x, wv[j].x);
                        fma2(acc[i * 8 + jh * 4 + j], xv[i].y, wv[j].y);
                    }
            }
        }
        if (kt < 61) {
            FILLZ(kt + 3, (kt + 3) & 3);
            asm volatile("cp.async.commit_group;");
        }
    }
    __syncthreads();

    // epilogue: split-k reduce across warp halves, add bias
    if (kbase) {   // warps 4-7 write partials
#pragma unroll
        for (int i = 0; i < 4; i++)
#pragma unroll
            for (int j = 0; j < 8; j++) {
                float lo, hi; unpack2(acc[i * 8 + j], lo, hi);
                sZp[(t0 + i) * 33 + c0 + j] = lo + hi;
            }
    }
    __syncthreads();
    if (!kbase) {  // warps 0-3 combine + bias
        float b2v[8];
#pragma unroll
        for (int j = 0; j < 8; j++) b2v[j] = g_b2[c0 + j];
#pragma unroll
        for (int i = 0; i < 4; i++)
#pragma unroll
            for (int j = 0; j < 8; j++) {
                float lo, hi; unpack2(acc[i * 8 + j], lo, hi);
                sZf[(t0 + i) * 33 + c0 + j] =
                    lo + hi + sZp[(t0 + i) * 33 + c0 + j] + b2v[j];
            }
    }
    // per-code norms
    {
        const float4* r = (const float4*)(scb + tid * 32);
        float s = 0.f;
#pragma unroll
        for (int j = 0; j < 8; j++) {
            float4 v = r[j];
            s += v.x * v.x + v.y * v.y + v.z * v.z + v.w * v.w;
        }
        scnorm[tid] = s;
    }
    __syncthreads();

    // argmin: 2 threads per token, 128 codes each
    {
        int tok = tid >> 1, half = tid & 1;
        ull z2[16];
        const float* zr = sZf + tok * 33;
#pragma unroll
        for (int j = 0; j < 16; j++)
            z2[j] = pack2(-2.f * zr[2 * j], -2.f * zr[2 * j + 1]);
        float best = 3.4e38f; int bestn = 0;
        int nbase = half * 128;
        for (int nn = 0; nn < 128; nn++) {
            int n = nbase + nn;
            const ulonglong2* cb2 = (const ulonglong2*)(scb + n * 32);
            ull a0 = 0ull, a1 = 0ull;
#pragma unroll
            for (int j = 0; j < 8; j++) {
                ulonglong2 c2 = cb2[j];
                fma2(a0, z2[2 * j], c2.x);
                fma2(a1, z2[2 * j + 1], c2.y);
            }
            float l0, h0, l1, h1;
            unpack2(a0, l0, h0); unpack2(a1, l1, h1);
            float d = scnorm[n] + ((l0 + h0) + (l1 + h1));
            if (d < best) { best = d; bestn = n; }
        }
        float obest = __shfl_down_sync(0xffffffffu, best, 1);
        int   obn   = __shfl_down_sync(0xffffffffu, bestn, 1);
        if (half == 0) {
            if (obest < best) bestn = obn;   // lower half wins ties (first index)
            sIdx[tok] = bestn;
        }
    }
    __syncthreads();

    // gather output rows from Table
    {
        const float4* T4 = (const float4*)g_Table;
        float4* out4 = (float4*)out;
        for (int e = tid; e < 128 * 512; e += 256) {
            int tok = e >> 9; int o4 = e & 511;
            out4[(size_t)(tok0 + tok) * 512 + o4] = T4[(size_t)sIdx[tok] * 512 + o4];
        }
        if (tid < 128) {
            long long pos = (long long)NMAIN + tok0 + tid;
            if (pos < out_elems) out[pos] = (float)sIdx[tid];
        }
        if (blockIdx.x == 0 && tid == 0) {
            long long pos = (long long)NMAIN + NTOK;
            if (pos < out_elems) out[pos] = 0.f;
        }
    }
}

// ================= launch =================
extern "C" void kernel_launch(void* const* d_in, const int* in_sizes, int n_in,
                              void* d_out, int out_size) {
    const float* x        = (const float*)d_in[0];
    const float* down_w   = (const float*)d_in[1];
    const float* down_b   = (const float*)d_in[2];
    const float* pin_w    = (const float*)d_in[3];
    const float* pin_b    = (const float*)d_in[4];
    const float* codebook = (const float*)d_in[5];
    const float* pout_w   = (const float*)d_in[6];
    const float* pout_b   = (const float*)d_in[7];
    const float* up_w     = (const float*)d_in[8];
    const float* up_b     = (const float*)d_in[9];
    float* out = (float*)d_out;

    cudaFuncSetAttribute(kZ, cudaFuncAttributeMaxDynamicSharedMemorySize, SMEM_Z);

    kPre1<<<384, 256>>>(down_w, pin_w, up_w, pout_w);
    kPre2<<<769, 256>>>(pin_w, down_b, pin_b, up_w, pout_b, up_b);
    kTable<<<2048, 256>>>(codebook);
    kZ<<<128, 256, SMEM_Z>>>(x, codebook, out, (long long)out_size);
}